// round 4
// baseline (speedup 1.0000x reference)
#include <cuda_runtime.h>
#include <cuda_bf16.h>
#include <math.h>

#define N_NODES 50000
#define N_EDGES 400000
#define HDIM 64
#define EDIM 8
#define MHID 128
#define RHID 128
#define TE 64    // edges per block in message kernel
#define PB 64    // nodes per block in projection kernel
#define GB 64    // nodes per block in fused GRU kernel

// Scratch (device globals: no allocation allowed)
__device__ float g_h[N_NODES * HDIM];
__device__ float g_agg[N_NODES * HDIM];
__device__ float g_P[N_NODES * 2 * MHID];   // [node][256]: 0..127 = h@W1a, 128..255 = h@W1b

__device__ __forceinline__ float sigmoidf(float x) { return 1.f / (1.f + expf(-x)); }

__global__ void init_kernel(const float* __restrict__ nf) {
    int i = blockIdx.x * blockDim.x + threadIdx.x;
    if (i < N_NODES * HDIM) { g_h[i] = nf[i]; g_agg[i] = 0.f; }
}

// ---------------------------------------------------------------------------
// Standalone projection (t=0 only): P[n] = h[n] @ [W1a | W1b]
// ---------------------------------------------------------------------------
__global__ __launch_bounds__(256) void proj_kernel(const float* __restrict__ W1) {
    __shared__ float sh[PB][HDIM];
    const int n0  = blockIdx.x * PB;
    const int tid = threadIdx.x;

    for (int i = tid; i < PB * HDIM; i += 256) {
        int r = i >> 6, c = i & 63;
        int node = n0 + r;
        sh[r][c] = (node < N_NODES) ? g_h[(long)node * HDIM + c] : 0.f;
    }
    __syncthreads();

    const int hc = tid & 31;
    const int nr = tid >> 5;
    const int j0 = hc * 8;
    const float* Wbase = (j0 < 128) ? (W1 + j0) : (W1 + 64 * MHID + (j0 - 128));

    float acc[8][8];
    #pragma unroll
    for (int n = 0; n < 8; n++)
        #pragma unroll
        for (int j = 0; j < 8; j++) acc[n][j] = 0.f;

    #pragma unroll 2
    for (int k = 0; k < HDIM; k++) {
        const float4* wp = reinterpret_cast<const float4*>(Wbase + (long)k * MHID);
        float4 wA = wp[0], wB = wp[1];
        #pragma unroll
        for (int n = 0; n < 8; n++) {
            float a = sh[nr + 8 * n][k];
            acc[n][0] = fmaf(a, wA.x, acc[n][0]);
            acc[n][1] = fmaf(a, wA.y, acc[n][1]);
            acc[n][2] = fmaf(a, wA.z, acc[n][2]);
            acc[n][3] = fmaf(a, wA.w, acc[n][3]);
            acc[n][4] = fmaf(a, wB.x, acc[n][4]);
            acc[n][5] = fmaf(a, wB.y, acc[n][5]);
            acc[n][6] = fmaf(a, wB.z, acc[n][6]);
            acc[n][7] = fmaf(a, wB.w, acc[n][7]);
        }
    }

    #pragma unroll
    for (int n = 0; n < 8; n++) {
        int node = n0 + nr + 8 * n;
        if (node < N_NODES) {
            float4* op = reinterpret_cast<float4*>(g_P + (long)node * 256 + j0);
            op[0] = make_float4(acc[n][0], acc[n][1], acc[n][2], acc[n][3]);
            op[1] = make_float4(acc[n][4], acc[n][5], acc[n][6], acc[n][7]);
        }
    }
}

// ---------------------------------------------------------------------------
// Message kernel (64 edges/block, 256 threads)
// Stage 2: hidden = relu(P[src] + P[dst] + ef@W1c + b1)  -> hid (stride 129)
// Stage 3: GEMM2 warp-uniform W2 loads: warp w -> cols 8w..8w+7,
//          lane -> edges lane, lane+32. red.v4 scatter.
// ---------------------------------------------------------------------------
__global__ __launch_bounds__(256) void msg_kernel(
    const float* __restrict__ ef,
    const int* __restrict__ src, const int* __restrict__ dst,
    const float* __restrict__ W1, const float* __restrict__ b1,
    const float* __restrict__ W2, const float* __restrict__ b2)
{
    __shared__ float hid[TE][129];
    __shared__ float sW1c[EDIM][MHID];
    __shared__ float sb1[MHID];
    __shared__ float sb2[HDIM];
    __shared__ int   ssrc[TE], sdst[TE];
    __shared__ float sef[TE][EDIM];

    const int e0  = blockIdx.x * TE;
    const int tid = threadIdx.x;

    if (tid < TE) { ssrc[tid] = src[e0 + tid]; sdst[tid] = dst[e0 + tid]; }
    for (int i = tid; i < TE * EDIM; i += 256)
        sef[i >> 3][i & 7] = ef[(long)e0 * EDIM + i];
    for (int i = tid; i < EDIM * MHID; i += 256)
        sW1c[i >> 7][i & 127] = W1[128 * MHID + i];
    if (tid < MHID) sb1[tid] = b1[tid];
    if (tid < HDIM) sb2[tid] = b2[tid];
    __syncthreads();

    // Stage 2
    {
        const int e  = tid >> 2;
        const int c0 = (tid & 3) * 32;
        const int s = ssrc[e], d = sdst[e];
        const float* ps = g_P + (long)s * 256 + c0;
        const float* pd = g_P + (long)d * 256 + 128 + c0;
        float efr[EDIM];
        #pragma unroll
        for (int k = 0; k < EDIM; k++) efr[k] = sef[e][k];

        #pragma unroll
        for (int j4 = 0; j4 < 8; j4++) {
            float4 a  = *reinterpret_cast<const float4*>(ps + j4 * 4);
            float4 bq = *reinterpret_cast<const float4*>(pd + j4 * 4);
            int c = c0 + j4 * 4;
            float v0 = a.x + bq.x + sb1[c + 0];
            float v1 = a.y + bq.y + sb1[c + 1];
            float v2 = a.z + bq.z + sb1[c + 2];
            float v3 = a.w + bq.w + sb1[c + 3];
            #pragma unroll
            for (int k = 0; k < EDIM; k++) {
                float e_k = efr[k];
                v0 = fmaf(e_k, sW1c[k][c + 0], v0);
                v1 = fmaf(e_k, sW1c[k][c + 1], v1);
                v2 = fmaf(e_k, sW1c[k][c + 2], v2);
                v3 = fmaf(e_k, sW1c[k][c + 3], v3);
            }
            hid[e][c + 0] = fmaxf(v0, 0.f);
            hid[e][c + 1] = fmaxf(v1, 0.f);
            hid[e][c + 2] = fmaxf(v2, 0.f);
            hid[e][c + 3] = fmaxf(v3, 0.f);
        }
    }
    __syncthreads();

    // Stage 3: warp w -> output cols c0=8w..8w+7; lane -> edges lane, lane+32
    const int w    = tid >> 5;
    const int lane = tid & 31;
    const int c0   = w * 8;

    float a0[8], a1[8];
    #pragma unroll
    for (int j = 0; j < 8; j++) { a0[j] = sb2[c0 + j]; a1[j] = a0[j]; }

    #pragma unroll 4
    for (int k = 0; k < MHID; k++) {
        // warp-uniform weight loads: one 128B line per warp
        float4 wA = __ldg(reinterpret_cast<const float4*>(W2 + (long)k * HDIM + c0));
        float4 wB = __ldg(reinterpret_cast<const float4*>(W2 + (long)k * HDIM + c0 + 4));
        float h0 = hid[lane][k];
        float h1 = hid[lane + 32][k];
        a0[0]=fmaf(h0,wA.x,a0[0]); a0[1]=fmaf(h0,wA.y,a0[1]); a0[2]=fmaf(h0,wA.z,a0[2]); a0[3]=fmaf(h0,wA.w,a0[3]);
        a0[4]=fmaf(h0,wB.x,a0[4]); a0[5]=fmaf(h0,wB.y,a0[5]); a0[6]=fmaf(h0,wB.z,a0[6]); a0[7]=fmaf(h0,wB.w,a0[7]);
        a1[0]=fmaf(h1,wA.x,a1[0]); a1[1]=fmaf(h1,wA.y,a1[1]); a1[2]=fmaf(h1,wA.z,a1[2]); a1[3]=fmaf(h1,wA.w,a1[3]);
        a1[4]=fmaf(h1,wB.x,a1[4]); a1[5]=fmaf(h1,wB.y,a1[5]); a1[6]=fmaf(h1,wB.z,a1[6]); a1[7]=fmaf(h1,wB.w,a1[7]);
    }

    {
        long d0 = sdst[lane], d1 = sdst[lane + 32];
        float* p0 = g_agg + d0 * HDIM + c0;
        float* p1 = g_agg + d1 * HDIM + c0;
        asm volatile("red.global.add.v4.f32 [%0], {%1, %2, %3, %4};"
                     :: "l"(p0), "f"(a0[0]), "f"(a0[1]), "f"(a0[2]), "f"(a0[3]) : "memory");
        asm volatile("red.global.add.v4.f32 [%0], {%1, %2, %3, %4};"
                     :: "l"(p0 + 4), "f"(a0[4]), "f"(a0[5]), "f"(a0[6]), "f"(a0[7]) : "memory");
        asm volatile("red.global.add.v4.f32 [%0], {%1, %2, %3, %4};"
                     :: "l"(p1), "f"(a1[0]), "f"(a1[1]), "f"(a1[2]), "f"(a1[3]) : "memory");
        asm volatile("red.global.add.v4.f32 [%0], {%1, %2, %3, %4};"
                     :: "l"(p1 + 4), "f"(a1[4]), "f"(a1[5]), "f"(a1[6]), "f"(a1[7]) : "memory");
    }
}

// ---------------------------------------------------------------------------
// Fused GRU (+ projection for next step OR readout). Weights staged through
// a 16KB smem chunk buffer -> inner loops are LDS-only (conflict-free).
// Warp w owns nodes {w, w+8, ..., w+56}; lane owns cols lane+32j.
// ---------------------------------------------------------------------------
__global__ __launch_bounds__(256) void gru_fused_kernel(
    const float* __restrict__ Wx, const float* __restrict__ Wh,
    const float* __restrict__ bg, const float* __restrict__ W1,
    const float* __restrict__ Wr1, const float* __restrict__ br1,
    const float* __restrict__ Wr2, const float* __restrict__ br2,
    float* __restrict__ out, int do_proj)
{
    __shared__ float sxh[GB][128];     // 32KB: cols 0..63 = x(agg), 64..127 = h_old
    __shared__ float wbuf[4096];       // 16KB chunk buffer
    const int tid  = threadIdx.x;
    const int lane = tid & 31;
    const int wid  = tid >> 5;
    const int n0   = blockIdx.x * GB;

    for (int i = tid; i < GB * 64; i += 256) {
        int r = i >> 6, c = i & 63;
        int node = n0 + r;
        float xv = 0.f, hv = 0.f;
        if (node < N_NODES) {
            long off = (long)node * HDIM + c;
            xv = g_agg[off];
            g_agg[off] = 0.f;
            hv = g_h[off];
        }
        sxh[r][c]      = xv;
        sxh[r][64 + c] = hv;
    }
    __syncthreads();

    float acc[8][4];    // z (j=0,1), r (j=2,3)
    float accx[8][2];   // candidate x-part (+bias)
    float acch[8][2];   // candidate h-part
    {
        float bz0 = bg[lane],       bz1 = bg[lane + 32];
        float br0 = bg[lane + 64],  brr = bg[lane + 96];
        float bc0 = bg[lane + 128], bc1 = bg[lane + 160];
        #pragma unroll
        for (int n = 0; n < 8; n++) {
            acc[n][0]=bz0; acc[n][1]=bz1; acc[n][2]=br0; acc[n][3]=brr;
            accx[n][0]=bc0; accx[n][1]=bc1; acch[n][0]=0.f; acch[n][1]=0.f;
        }
    }

    // --- x @ Wx, chunked (4 chunks of 16 rows x 192 cols = 12KB) ---
    for (int kc = 0; kc < 4; kc++) {
        for (int i = tid; i < 16 * 48; i += 256)
            reinterpret_cast<float4*>(wbuf)[i] =
                reinterpret_cast<const float4*>(Wx + kc * 16 * 192)[i];
        __syncthreads();
        #pragma unroll 4
        for (int kk = 0; kk < 16; kk++) {
            const float* wr = wbuf + kk * 192;
            float w0=wr[lane], w1=wr[lane+32], w2=wr[lane+64], w3=wr[lane+96];
            float w4=wr[lane+128], w5=wr[lane+160];
            int k = kc * 16 + kk;
            #pragma unroll
            for (int n = 0; n < 8; n++) {
                float a = sxh[wid + 8*n][k];
                acc[n][0]=fmaf(a,w0,acc[n][0]); acc[n][1]=fmaf(a,w1,acc[n][1]);
                acc[n][2]=fmaf(a,w2,acc[n][2]); acc[n][3]=fmaf(a,w3,acc[n][3]);
                accx[n][0]=fmaf(a,w4,accx[n][0]); accx[n][1]=fmaf(a,w5,accx[n][1]);
            }
        }
        __syncthreads();
    }
    // --- h @ Wh, chunked ---
    for (int kc = 0; kc < 4; kc++) {
        for (int i = tid; i < 16 * 48; i += 256)
            reinterpret_cast<float4*>(wbuf)[i] =
                reinterpret_cast<const float4*>(Wh + kc * 16 * 192)[i];
        __syncthreads();
        #pragma unroll 4
        for (int kk = 0; kk < 16; kk++) {
            const float* wr = wbuf + kk * 192;
            float w0=wr[lane], w1=wr[lane+32], w2=wr[lane+64], w3=wr[lane+96];
            float w4=wr[lane+128], w5=wr[lane+160];
            int k = 64 + kc * 16 + kk;
            #pragma unroll
            for (int n = 0; n < 8; n++) {
                float a = sxh[wid + 8*n][k];
                acc[n][0]=fmaf(a,w0,acc[n][0]); acc[n][1]=fmaf(a,w1,acc[n][1]);
                acc[n][2]=fmaf(a,w2,acc[n][2]); acc[n][3]=fmaf(a,w3,acc[n][3]);
                acch[n][0]=fmaf(a,w4,acch[n][0]); acch[n][1]=fmaf(a,w5,acch[n][1]);
            }
        }
        __syncthreads();
    }

    // --- elementwise GRU; new h -> sxh[.][0..63] and g_h ---
    #pragma unroll
    for (int n = 0; n < 8; n++) {
        int r = wid + 8*n;
        int node = n0 + r;
        #pragma unroll
        for (int j = 0; j < 2; j++) {
            int c = lane + 32*j;
            float z  = sigmoidf(acc[n][j]);
            float rr = sigmoidf(acc[n][2 + j]);
            float hc = tanhf(accx[n][j] + rr * acch[n][j]);
            float hold = sxh[r][64 + c];
            float hnew = z * hold + (1.f - z) * hc;
            sxh[r][c] = hnew;
            if (node < N_NODES) g_h[(long)node * HDIM + c] = hnew;
        }
    }
    __syncthreads();

    if (do_proj) {
        // P = h_new @ Wc, Wc[k][c] = (c<128) ? W1[k][c] : W1[64+k][c-128]
        // 4 chunks of 16 rows x 256 cols = 16KB.
        const int j0 = lane * 8;
        float p[8][8];
        #pragma unroll
        for (int n = 0; n < 8; n++)
            #pragma unroll
            for (int j = 0; j < 8; j++) p[n][j] = 0.f;

        for (int kc = 0; kc < 4; kc++) {
            for (int i = tid; i < 16 * 64; i += 256) {     // float4 over 16x256
                int row = i >> 6;            // 0..15
                int cq  = (i & 63) * 4;      // 0..252
                int k   = kc * 16 + row;
                const float* s = (cq < 128) ? (W1 + (long)k * MHID + cq)
                                            : (W1 + (long)(64 + k) * MHID + (cq - 128));
                reinterpret_cast<float4*>(wbuf)[i] = *reinterpret_cast<const float4*>(s);
            }
            __syncthreads();
            #pragma unroll 4
            for (int kk = 0; kk < 16; kk++) {
                const float4* wp = reinterpret_cast<const float4*>(wbuf + kk * 256 + j0);
                float4 wA = wp[0], wB = wp[1];
                int k = kc * 16 + kk;
                #pragma unroll
                for (int n = 0; n < 8; n++) {
                    float a = sxh[wid + 8*n][k];
                    p[n][0]=fmaf(a,wA.x,p[n][0]); p[n][1]=fmaf(a,wA.y,p[n][1]);
                    p[n][2]=fmaf(a,wA.z,p[n][2]); p[n][3]=fmaf(a,wA.w,p[n][3]);
                    p[n][4]=fmaf(a,wB.x,p[n][4]); p[n][5]=fmaf(a,wB.y,p[n][5]);
                    p[n][6]=fmaf(a,wB.z,p[n][6]); p[n][7]=fmaf(a,wB.w,p[n][7]);
                }
            }
            __syncthreads();
        }
        #pragma unroll
        for (int n = 0; n < 8; n++) {
            int node = n0 + wid + 8*n;
            if (node < N_NODES) {
                float4* op = reinterpret_cast<float4*>(g_P + (long)node * 256 + j0);
                op[0] = make_float4(p[n][0], p[n][1], p[n][2], p[n][3]);
                op[1] = make_float4(p[n][4], p[n][5], p[n][6], p[n][7]);
            }
        }
    } else {
        // readout: relu(h_new @ Wr1 + br1) @ Wr2 + br2; Wr1 chunks 16x128 = 8KB
        float racc[8][4];
        #pragma unroll
        for (int n = 0; n < 8; n++)
            #pragma unroll
            for (int j = 0; j < 4; j++) racc[n][j] = 0.f;

        for (int kc = 0; kc < 4; kc++) {
            for (int i = tid; i < 16 * 32; i += 256)
                reinterpret_cast<float4*>(wbuf)[i] =
                    reinterpret_cast<const float4*>(Wr1 + kc * 16 * RHID)[i];
            __syncthreads();
            #pragma unroll 4
            for (int kk = 0; kk < 16; kk++) {
                const float* wr = wbuf + kk * 128;
                float w0=wr[lane], w1=wr[lane+32], w2=wr[lane+64], w3=wr[lane+96];
                int k = kc * 16 + kk;
                #pragma unroll
                for (int n = 0; n < 8; n++) {
                    float a = sxh[wid + 8*n][k];
                    racc[n][0]=fmaf(a,w0,racc[n][0]); racc[n][1]=fmaf(a,w1,racc[n][1]);
                    racc[n][2]=fmaf(a,w2,racc[n][2]); racc[n][3]=fmaf(a,w3,racc[n][3]);
                }
            }
            __syncthreads();
        }
        float bb[4], w2v[4];
        #pragma unroll
        for (int j = 0; j < 4; j++) {
            bb[j]  = br1[lane + 32*j];
            w2v[j] = Wr2[lane + 32*j];
        }
        float part[8];
        #pragma unroll
        for (int n = 0; n < 8; n++) {
            float s = 0.f;
            #pragma unroll
            for (int j = 0; j < 4; j++)
                s = fmaf(fmaxf(racc[n][j] + bb[j], 0.f), w2v[j], s);
            part[n] = s;
        }
        #pragma unroll
        for (int off = 16; off; off >>= 1)
            #pragma unroll
            for (int n = 0; n < 8; n++)
                part[n] += __shfl_xor_sync(0xffffffffu, part[n], off);
        if (lane == 0) {
            float bo = br2[0];
            #pragma unroll
            for (int n = 0; n < 8; n++) {
                int node = n0 + wid + 8*n;
                if (node < N_NODES) out[node] = part[n] + bo;
            }
        }
    }
}

extern "C" void kernel_launch(void* const* d_in, const int* in_sizes, int n_in,
                              void* d_out, int out_size) {
    const float* nf  = (const float*)d_in[0];
    const float* ef  = (const float*)d_in[1];
    const int*   src = (const int*)  d_in[2];
    const int*   dst = (const int*)  d_in[3];
    const float* W1  = (const float*)d_in[4];
    const float* b1  = (const float*)d_in[5];
    const float* W2  = (const float*)d_in[6];
    const float* b2  = (const float*)d_in[7];
    const float* Wx  = (const float*)d_in[8];
    const float* Wh  = (const float*)d_in[9];
    const float* bg  = (const float*)d_in[10];
    const float* Wr1 = (const float*)d_in[11];
    const float* br1 = (const float*)d_in[12];
    const float* Wr2 = (const float*)d_in[13];
    const float* br2 = (const float*)d_in[14];
    float* out = (float*)d_out;

    const int nb_nh = (N_NODES * HDIM + 255) / 256;
    const int nproj = (N_NODES + PB - 1) / PB;     // 782
    const int ngru  = (N_NODES + GB - 1) / GB;     // 782

    init_kernel<<<nb_nh, 256>>>(nf);
    proj_kernel<<<nproj, 256>>>(W1);
    // t = 0
    msg_kernel<<<N_EDGES / TE, 256>>>(ef, src, dst, W1, b1, W2, b2);
    gru_fused_kernel<<<ngru, 256>>>(Wx, Wh, bg, W1, Wr1, br1, Wr2, br2, out, 1);
    // t = 1 (readout fused)
    msg_kernel<<<N_EDGES / TE, 256>>>(ef, src, dst, W1, b1, W2, b2);
    gru_fused_kernel<<<ngru, 256>>>(Wx, Wh, bg, W1, Wr1, br1, Wr2, br2, out, 0);
}

// round 5
// speedup vs baseline: 1.0722x; 1.0722x over previous
#include <cuda_runtime.h>
#include <cuda_bf16.h>
#include <math.h>

#define N_NODES 50000
#define N_EDGES 400000
#define HDIM 64
#define EDIM 8
#define MHID 128
#define RHID 128
#define TE 64    // edges per block in message kernel
#define PB 64    // nodes per block in projection kernel
#define GB 32    // nodes per block in fused GRU kernel

// Scratch (device globals: no allocation allowed)
__device__ float g_h[N_NODES * HDIM];
__device__ float g_agg[N_NODES * HDIM];
__device__ float g_P[N_NODES * 2 * MHID];   // [node][256]: 0..127 = h@W1a, 128..255 = h@W1b

__device__ __forceinline__ float sigmoidf(float x) { return 1.f / (1.f + expf(-x)); }

__global__ void init_kernel(const float* __restrict__ nf) {
    int i = blockIdx.x * blockDim.x + threadIdx.x;
    if (i < N_NODES * HDIM) { g_h[i] = nf[i]; g_agg[i] = 0.f; }
}

// ---------------------------------------------------------------------------
// Standalone projection (t=0 only): P[n] = h[n] @ [W1a | W1b]
// ---------------------------------------------------------------------------
__global__ __launch_bounds__(256) void proj_kernel(const float* __restrict__ W1) {
    __shared__ float sh[PB][HDIM];
    const int n0  = blockIdx.x * PB;
    const int tid = threadIdx.x;

    for (int i = tid; i < PB * HDIM; i += 256) {
        int r = i >> 6, c = i & 63;
        int node = n0 + r;
        sh[r][c] = (node < N_NODES) ? g_h[(long)node * HDIM + c] : 0.f;
    }
    __syncthreads();

    const int hc = tid & 31;
    const int nr = tid >> 5;
    const int j0 = hc * 8;
    const float* Wbase = (j0 < 128) ? (W1 + j0) : (W1 + 64 * MHID + (j0 - 128));

    float acc[8][8];
    #pragma unroll
    for (int n = 0; n < 8; n++)
        #pragma unroll
        for (int j = 0; j < 8; j++) acc[n][j] = 0.f;

    #pragma unroll 2
    for (int k = 0; k < HDIM; k++) {
        const float4* wp = reinterpret_cast<const float4*>(Wbase + (long)k * MHID);
        float4 wA = wp[0], wB = wp[1];
        #pragma unroll
        for (int n = 0; n < 8; n++) {
            float a = sh[nr + 8 * n][k];
            acc[n][0] = fmaf(a, wA.x, acc[n][0]);
            acc[n][1] = fmaf(a, wA.y, acc[n][1]);
            acc[n][2] = fmaf(a, wA.z, acc[n][2]);
            acc[n][3] = fmaf(a, wA.w, acc[n][3]);
            acc[n][4] = fmaf(a, wB.x, acc[n][4]);
            acc[n][5] = fmaf(a, wB.y, acc[n][5]);
            acc[n][6] = fmaf(a, wB.z, acc[n][6]);
            acc[n][7] = fmaf(a, wB.w, acc[n][7]);
        }
    }

    #pragma unroll
    for (int n = 0; n < 8; n++) {
        int node = n0 + nr + 8 * n;
        if (node < N_NODES) {
            float4* op = reinterpret_cast<float4*>(g_P + (long)node * 256 + j0);
            op[0] = make_float4(acc[n][0], acc[n][1], acc[n][2], acc[n][3]);
            op[1] = make_float4(acc[n][4], acc[n][5], acc[n][6], acc[n][7]);
        }
    }
}

// ---------------------------------------------------------------------------
// Message kernel (64 edges/block, 256 threads) — R3 layout (best measured).
// ---------------------------------------------------------------------------
__global__ __launch_bounds__(256) void msg_kernel(
    const float* __restrict__ ef,
    const int* __restrict__ src, const int* __restrict__ dst,
    const float* __restrict__ W1, const float* __restrict__ b1,
    const float* __restrict__ W2, const float* __restrict__ b2)
{
    __shared__ float hid[TE][132];
    __shared__ float sW1c[EDIM][MHID];
    __shared__ float sb1[MHID];
    __shared__ float sb2[HDIM];
    __shared__ int   ssrc[TE], sdst[TE];
    __shared__ float sef[TE][EDIM];

    const int e0  = blockIdx.x * TE;
    const int tid = threadIdx.x;

    if (tid < TE) { ssrc[tid] = src[e0 + tid]; sdst[tid] = dst[e0 + tid]; }
    for (int i = tid; i < TE * EDIM; i += 256)
        sef[i >> 3][i & 7] = ef[(long)e0 * EDIM + i];
    for (int i = tid; i < EDIM * MHID; i += 256)
        sW1c[i >> 7][i & 127] = W1[128 * MHID + i];
    if (tid < MHID) sb1[tid] = b1[tid];
    if (tid < HDIM) sb2[tid] = b2[tid];
    __syncthreads();

    {
        const int e  = tid >> 2;
        const int c0 = (tid & 3) * 32;
        const int s = ssrc[e], d = sdst[e];
        const float* ps = g_P + (long)s * 256 + c0;
        const float* pd = g_P + (long)d * 256 + 128 + c0;
        float efr[EDIM];
        #pragma unroll
        for (int k = 0; k < EDIM; k++) efr[k] = sef[e][k];

        #pragma unroll
        for (int j4 = 0; j4 < 8; j4++) {
            float4 a  = *reinterpret_cast<const float4*>(ps + j4 * 4);
            float4 bq = *reinterpret_cast<const float4*>(pd + j4 * 4);
            int c = c0 + j4 * 4;
            float v0 = a.x + bq.x + sb1[c + 0];
            float v1 = a.y + bq.y + sb1[c + 1];
            float v2 = a.z + bq.z + sb1[c + 2];
            float v3 = a.w + bq.w + sb1[c + 3];
            #pragma unroll
            for (int k = 0; k < EDIM; k++) {
                float e_k = efr[k];
                v0 = fmaf(e_k, sW1c[k][c + 0], v0);
                v1 = fmaf(e_k, sW1c[k][c + 1], v1);
                v2 = fmaf(e_k, sW1c[k][c + 2], v2);
                v3 = fmaf(e_k, sW1c[k][c + 3], v3);
            }
            hid[e][c + 0] = fmaxf(v0, 0.f);
            hid[e][c + 1] = fmaxf(v1, 0.f);
            hid[e][c + 2] = fmaxf(v2, 0.f);
            hid[e][c + 3] = fmaxf(v3, 0.f);
        }
    }
    __syncthreads();

    const int er = tid >> 4;
    const int oc = tid & 15;
    float m0[4], m1[4], m2[4], m3[4];
    {
        m0[0]=sb2[oc*4+0]; m0[1]=sb2[oc*4+1]; m0[2]=sb2[oc*4+2]; m0[3]=sb2[oc*4+3];
        #pragma unroll
        for (int j = 0; j < 4; j++) { m1[j]=m0[j]; m2[j]=m0[j]; m3[j]=m0[j]; }
    }

    #pragma unroll 8
    for (int k = 0; k < MHID; k++) {
        float4 w = *reinterpret_cast<const float4*>(W2 + (long)k * HDIM + oc * 4);
        float a0 = hid[4*er + 0][k];
        float a1 = hid[4*er + 1][k];
        float a2 = hid[4*er + 2][k];
        float a3 = hid[4*er + 3][k];
        m0[0]=fmaf(a0,w.x,m0[0]); m0[1]=fmaf(a0,w.y,m0[1]); m0[2]=fmaf(a0,w.z,m0[2]); m0[3]=fmaf(a0,w.w,m0[3]);
        m1[0]=fmaf(a1,w.x,m1[0]); m1[1]=fmaf(a1,w.y,m1[1]); m1[2]=fmaf(a1,w.z,m1[2]); m1[3]=fmaf(a1,w.w,m1[3]);
        m2[0]=fmaf(a2,w.x,m2[0]); m2[1]=fmaf(a2,w.y,m2[1]); m2[2]=fmaf(a2,w.z,m2[2]); m2[3]=fmaf(a2,w.w,m2[3]);
        m3[0]=fmaf(a3,w.x,m3[0]); m3[1]=fmaf(a3,w.y,m3[1]); m3[2]=fmaf(a3,w.z,m3[2]); m3[3]=fmaf(a3,w.w,m3[3]);
    }

    #pragma unroll
    for (int i = 0; i < 4; i++) {
        long d = sdst[4*er + i];
        float* p = g_agg + d * HDIM + oc * 4;
        float* mv = (i == 0) ? m0 : (i == 1) ? m1 : (i == 2) ? m2 : m3;
        asm volatile("red.global.add.v4.f32 [%0], {%1, %2, %3, %4};"
                     :: "l"(p), "f"(mv[0]), "f"(mv[1]), "f"(mv[2]), "f"(mv[3])
                     : "memory");
    }
}

// ---------------------------------------------------------------------------
// Fused GRU (+ projection for next step OR readout).
// GB=32 nodes/block, 256 threads. Warp w owns nodes {w, w+8, w+16, w+24};
// lane owns gate cols lane+32j. Small per-thread tile -> no spills, higher occ.
// Also consumes-and-zeroes g_agg (graph-replay invariant).
// ---------------------------------------------------------------------------
__global__ __launch_bounds__(256) void gru_fused_kernel(
    const float* __restrict__ Wx, const float* __restrict__ Wh,
    const float* __restrict__ bg, const float* __restrict__ W1,
    const float* __restrict__ Wr1, const float* __restrict__ br1,
    const float* __restrict__ Wr2, const float* __restrict__ br2,
    float* __restrict__ out, int do_proj)
{
    __shared__ float sxh[GB][128];   // 16KB: cols 0..63 = x(agg), 64..127 = h_old
    const int tid  = threadIdx.x;
    const int lane = tid & 31;
    const int wid  = tid >> 5;
    const int n0   = blockIdx.x * GB;

    for (int i = tid; i < GB * 64; i += 256) {
        int r = i >> 6, c = i & 63;
        int node = n0 + r;
        float xv = 0.f, hv = 0.f;
        if (node < N_NODES) {
            long off = (long)node * HDIM + c;
            xv = g_agg[off];
            g_agg[off] = 0.f;
            hv = g_h[off];
        }
        sxh[r][c]      = xv;
        sxh[r][64 + c] = hv;
    }
    __syncthreads();

    float acc[4][4];    // z (j=0,1), r (j=2,3)
    float accx[4][2];   // candidate x-part (+bias)
    float acch[4][2];   // candidate h-part
    {
        float bz0 = bg[lane],       bz1 = bg[lane + 32];
        float br0 = bg[lane + 64],  brr = bg[lane + 96];
        float bc0 = bg[lane + 128], bc1 = bg[lane + 160];
        #pragma unroll
        for (int n = 0; n < 4; n++) {
            acc[n][0]=bz0; acc[n][1]=bz1; acc[n][2]=br0; acc[n][3]=brr;
            accx[n][0]=bc0; accx[n][1]=bc1; acch[n][0]=0.f; acch[n][1]=0.f;
        }
    }

    #pragma unroll 4
    for (int k = 0; k < 64; k++) {           // x @ Wx
        const float* wr = Wx + (long)k * 192;
        float w0=wr[lane], w1=wr[lane+32], w2=wr[lane+64], w3=wr[lane+96];
        float w4=wr[lane+128], w5=wr[lane+160];
        #pragma unroll
        for (int n = 0; n < 4; n++) {
            float a = sxh[wid + 8*n][k];
            acc[n][0]=fmaf(a,w0,acc[n][0]); acc[n][1]=fmaf(a,w1,acc[n][1]);
            acc[n][2]=fmaf(a,w2,acc[n][2]); acc[n][3]=fmaf(a,w3,acc[n][3]);
            accx[n][0]=fmaf(a,w4,accx[n][0]); accx[n][1]=fmaf(a,w5,accx[n][1]);
        }
    }
    #pragma unroll 4
    for (int k = 0; k < 64; k++) {           // h @ Wh
        const float* wr = Wh + (long)k * 192;
        float w0=wr[lane], w1=wr[lane+32], w2=wr[lane+64], w3=wr[lane+96];
        float w4=wr[lane+128], w5=wr[lane+160];
        #pragma unroll
        for (int n = 0; n < 4; n++) {
            float a = sxh[wid + 8*n][64 + k];
            acc[n][0]=fmaf(a,w0,acc[n][0]); acc[n][1]=fmaf(a,w1,acc[n][1]);
            acc[n][2]=fmaf(a,w2,acc[n][2]); acc[n][3]=fmaf(a,w3,acc[n][3]);
            acch[n][0]=fmaf(a,w4,acch[n][0]); acch[n][1]=fmaf(a,w5,acch[n][1]);
        }
    }
    __syncthreads();   // GEMM smem reads done before overwriting x-region

    // --- elementwise GRU; new h -> sxh[.][0..63] and g_h ---
    #pragma unroll
    for (int n = 0; n < 4; n++) {
        int r = wid + 8*n;
        int node = n0 + r;
        #pragma unroll
        for (int j = 0; j < 2; j++) {
            int c = lane + 32*j;
            float z  = sigmoidf(acc[n][j]);
            float rr = sigmoidf(acc[n][2 + j]);
            float hc = tanhf(accx[n][j] + rr * acch[n][j]);
            float hold = sxh[r][64 + c];
            float hnew = z * hold + (1.f - z) * hc;
            sxh[r][c] = hnew;
            if (node < N_NODES) g_h[(long)node * HDIM + c] = hnew;
        }
    }
    __syncthreads();

    if (do_proj) {
        // P = h_new @ [W1a | W1b]; lane -> 8 cols, warp -> 4 nodes
        const int j0 = lane * 8;
        const float* Wbase = (j0 < 128) ? (W1 + j0) : (W1 + 64 * MHID + (j0 - 128));
        float p[4][8];
        #pragma unroll
        for (int n = 0; n < 4; n++)
            #pragma unroll
            for (int j = 0; j < 8; j++) p[n][j] = 0.f;

        #pragma unroll 4
        for (int k = 0; k < 64; k++) {
            const float4* wp = reinterpret_cast<const float4*>(Wbase + (long)k * MHID);
            float4 wA = wp[0], wB = wp[1];
            #pragma unroll
            for (int n = 0; n < 4; n++) {
                float a = sxh[wid + 8*n][k];
                p[n][0]=fmaf(a,wA.x,p[n][0]); p[n][1]=fmaf(a,wA.y,p[n][1]);
                p[n][2]=fmaf(a,wA.z,p[n][2]); p[n][3]=fmaf(a,wA.w,p[n][3]);
                p[n][4]=fmaf(a,wB.x,p[n][4]); p[n][5]=fmaf(a,wB.y,p[n][5]);
                p[n][6]=fmaf(a,wB.z,p[n][6]); p[n][7]=fmaf(a,wB.w,p[n][7]);
            }
        }
        #pragma unroll
        for (int n = 0; n < 4; n++) {
            int node = n0 + wid + 8*n;
            if (node < N_NODES) {
                float4* op = reinterpret_cast<float4*>(g_P + (long)node * 256 + j0);
                op[0] = make_float4(p[n][0], p[n][1], p[n][2], p[n][3]);
                op[1] = make_float4(p[n][4], p[n][5], p[n][6], p[n][7]);
            }
        }
    } else {
        // readout: relu(h_new @ Wr1 + br1) @ Wr2 + br2
        float racc[4][4];
        #pragma unroll
        for (int n = 0; n < 4; n++)
            #pragma unroll
            for (int j = 0; j < 4; j++) racc[n][j] = 0.f;

        #pragma unroll 4
        for (int k = 0; k < 64; k++) {
            const float* wr = Wr1 + (long)k * RHID;
            float w0=wr[lane], w1=wr[lane+32], w2=wr[lane+64], w3=wr[lane+96];
            #pragma unroll
            for (int n = 0; n < 4; n++) {
                float a = sxh[wid + 8*n][k];
                racc[n][0]=fmaf(a,w0,racc[n][0]); racc[n][1]=fmaf(a,w1,racc[n][1]);
                racc[n][2]=fmaf(a,w2,racc[n][2]); racc[n][3]=fmaf(a,w3,racc[n][3]);
            }
        }
        float bb[4], w2v[4];
        #pragma unroll
        for (int j = 0; j < 4; j++) {
            bb[j]  = br1[lane + 32*j];
            w2v[j] = Wr2[lane + 32*j];
        }
        float part[4];
        #pragma unroll
        for (int n = 0; n < 4; n++) {
            float s = 0.f;
            #pragma unroll
            for (int j = 0; j < 4; j++)
                s = fmaf(fmaxf(racc[n][j] + bb[j], 0.f), w2v[j], s);
            part[n] = s;
        }
        #pragma unroll
        for (int off = 16; off; off >>= 1)
            #pragma unroll
            for (int n = 0; n < 4; n++)
                part[n] += __shfl_xor_sync(0xffffffffu, part[n], off);
        if (lane == 0) {
            float bo = br2[0];
            #pragma unroll
            for (int n = 0; n < 4; n++) {
                int node = n0 + wid + 8*n;
                if (node < N_NODES) out[node] = part[n] + bo;
            }
        }
    }
}

extern "C" void kernel_launch(void* const* d_in, const int* in_sizes, int n_in,
                              void* d_out, int out_size) {
    const float* nf  = (const float*)d_in[0];
    const float* ef  = (const float*)d_in[1];
    const int*   src = (const int*)  d_in[2];
    const int*   dst = (const int*)  d_in[3];
    const float* W1  = (const float*)d_in[4];
    const float* b1  = (const float*)d_in[5];
    const float* W2  = (const float*)d_in[6];
    const float* b2  = (const float*)d_in[7];
    const float* Wx  = (const float*)d_in[8];
    const float* Wh  = (const float*)d_in[9];
    const float* bg  = (const float*)d_in[10];
    const float* Wr1 = (const float*)d_in[11];
    const float* br1 = (const float*)d_in[12];
    const float* Wr2 = (const float*)d_in[13];
    const float* br2 = (const float*)d_in[14];
    float* out = (float*)d_out;

    const int nb_nh = (N_NODES * HDIM + 255) / 256;
    const int nproj = (N_NODES + PB - 1) / PB;     // 782
    const int ngru  = (N_NODES + GB - 1) / GB;     // 1563

    init_kernel<<<nb_nh, 256>>>(nf);
    proj_kernel<<<nproj, 256>>>(W1);
    // t = 0
    msg_kernel<<<N_EDGES / TE, 256>>>(ef, src, dst, W1, b1, W2, b2);
    gru_fused_kernel<<<ngru, 256>>>(Wx, Wh, bg, W1, Wr1, br1, Wr2, br2, out, 1);
    // t = 1 (readout fused)
    msg_kernel<<<N_EDGES / TE, 256>>>(ef, src, dst, W1, b1, W2, b2);
    gru_fused_kernel<<<ngru, 256>>>(Wx, Wh, bg, W1, Wr1, br1, Wr2, br2, out, 0);
}

// round 6
// speedup vs baseline: 1.2296x; 1.1468x over previous
#include <cuda_runtime.h>
#include <cuda_bf16.h>
#include <math.h>

#define N_NODES 50000
#define N_EDGES 400000
#define HDIM 64
#define EDIM 8
#define MHID 128
#define RHID 128
#define PB 64    // nodes per block in projection kernel
#define GB 32    // nodes per block in fused GRU kernel

typedef unsigned long long u64;

// Scratch (device globals: no allocation allowed)
__device__ float g_h[N_NODES * HDIM];
__device__ float g_aggh[N_NODES * MHID];      // 128-dim hidden aggregation
__device__ float g_P[N_NODES * 2 * MHID];     // [node][256]
__device__ float g_deg[N_NODES];
__device__ u64   g_Wg2[64 * 192];             // k-pairs of WgA = W2@Wx  [128x192]
__device__ u64   g_Whp[32 * 192];             // k-pairs of Wh [64x192]
__device__ u64   g_Wr1p[32 * 128];            // k-pairs of Wr1 [64x128]
__device__ float g_bvec[192];                 // b2 @ Wx

__device__ __forceinline__ float sigmoidf(float x) { return 1.f / (1.f + expf(-x)); }
__device__ __forceinline__ u64 pack2(float lo, float hi) {
    u64 r; asm("mov.b64 %0, {%1, %2};" : "=l"(r) : "f"(lo), "f"(hi)); return r;
}
__device__ __forceinline__ void unpack2(u64 v, float& lo, float& hi) {
    asm("mov.b64 {%0, %1}, %2;" : "=f"(lo), "=f"(hi) : "l"(v));
}
__device__ __forceinline__ u64 fma2(u64 a, u64 b, u64 c) {
    u64 d; asm("fma.rn.f32x2 %0, %1, %2, %3;" : "=l"(d) : "l"(a), "l"(b), "l"(c)); return d;
}

__global__ void init_kernel(const float* __restrict__ nf) {
    int i = blockIdx.x * blockDim.x + threadIdx.x;
    if (i < N_NODES * MHID) g_aggh[i] = 0.f;
    if (i < N_NODES * HDIM) g_h[i] = nf[i];
    if (i < N_NODES) g_deg[i] = 0.f;
}

__global__ void deg_kernel(const int* __restrict__ dst) {
    int i = blockIdx.x * blockDim.x + threadIdx.x;
    if (i < N_EDGES) atomicAdd(&g_deg[dst[i]], 1.0f);
}

// WgA[k][j] = sum_c W2[k][c] * Wx[c][j]; store k-pairs packed.
__global__ __launch_bounds__(256) void prep_wg(const float* __restrict__ W2,
                                               const float* __restrict__ Wx) {
    int t = blockIdx.x * blockDim.x + threadIdx.x;
    if (t >= 64 * 192) return;
    int k2 = t / 192, j = t % 192;
    float s0 = 0.f, s1 = 0.f;
    for (int c = 0; c < 64; c++) {
        float w = Wx[c * 192 + j];
        s0 = fmaf(W2[(2 * k2) * 64 + c], w, s0);
        s1 = fmaf(W2[(2 * k2 + 1) * 64 + c], w, s1);
    }
    g_Wg2[k2 * 192 + j] = pack2(s0, s1);
}

// Pack Wh, Wr1 into k-pairs; compute bvec = b2 @ Wx.
__global__ __launch_bounds__(256) void prep_pack(const float* __restrict__ Wh,
                                                 const float* __restrict__ Wr1,
                                                 const float* __restrict__ b2,
                                                 const float* __restrict__ Wx) {
    int t = blockIdx.x * blockDim.x + threadIdx.x;
    if (t < 32 * 192) {
        int i = t / 192, j = t % 192;
        g_Whp[t] = pack2(Wh[(2 * i) * 192 + j], Wh[(2 * i + 1) * 192 + j]);
    } else if (t < 32 * 192 + 32 * 128) {
        int u = t - 32 * 192;
        int i = u / 128, j = u % 128;
        g_Wr1p[u] = pack2(Wr1[(2 * i) * 128 + j], Wr1[(2 * i + 1) * 128 + j]);
    } else if (t < 32 * 192 + 32 * 128 + 192) {
        int j = t - (32 * 192 + 32 * 128);
        float s = 0.f;
        for (int c = 0; c < 64; c++) s = fmaf(b2[c], Wx[c * 192 + j], s);
        g_bvec[j] = s;
    }
}

// ---------------------------------------------------------------------------
// Standalone projection (t=0 only): P[n] = h[n] @ [W1a | W1b]
// ---------------------------------------------------------------------------
__global__ __launch_bounds__(256) void proj_kernel(const float* __restrict__ W1) {
    __shared__ float sh[PB][HDIM];
    const int n0  = blockIdx.x * PB;
    const int tid = threadIdx.x;

    for (int i = tid; i < PB * HDIM; i += 256) {
        int r = i >> 6, c = i & 63;
        int node = n0 + r;
        sh[r][c] = (node < N_NODES) ? g_h[(long)node * HDIM + c] : 0.f;
    }
    __syncthreads();

    const int hc = tid & 31;
    const int nr = tid >> 5;
    const int j0 = hc * 8;
    const float* Wbase = (j0 < 128) ? (W1 + j0) : (W1 + 64 * MHID + (j0 - 128));

    float acc[8][8];
    #pragma unroll
    for (int n = 0; n < 8; n++)
        #pragma unroll
        for (int j = 0; j < 8; j++) acc[n][j] = 0.f;

    #pragma unroll 2
    for (int k = 0; k < HDIM; k++) {
        const float4* wp = reinterpret_cast<const float4*>(Wbase + (long)k * MHID);
        float4 wA = wp[0], wB = wp[1];
        #pragma unroll
        for (int n = 0; n < 8; n++) {
            float a = sh[nr + 8 * n][k];
            acc[n][0] = fmaf(a, wA.x, acc[n][0]);
            acc[n][1] = fmaf(a, wA.y, acc[n][1]);
            acc[n][2] = fmaf(a, wA.z, acc[n][2]);
            acc[n][3] = fmaf(a, wA.w, acc[n][3]);
            acc[n][4] = fmaf(a, wB.x, acc[n][4]);
            acc[n][5] = fmaf(a, wB.y, acc[n][5]);
            acc[n][6] = fmaf(a, wB.z, acc[n][6]);
            acc[n][7] = fmaf(a, wB.w, acc[n][7]);
        }
    }

    #pragma unroll
    for (int n = 0; n < 8; n++) {
        int node = n0 + nr + 8 * n;
        if (node < N_NODES) {
            float4* op = reinterpret_cast<float4*>(g_P + (long)node * 256 + j0);
            op[0] = make_float4(acc[n][0], acc[n][1], acc[n][2], acc[n][3]);
            op[1] = make_float4(acc[n][4], acc[n][5], acc[n][6], acc[n][7]);
        }
    }
}

// ---------------------------------------------------------------------------
// Message kernel v2 (32 edges/block, 256 threads; 8 threads x 16 cols per edge):
//   hidden = relu(P[src][0:128] + P[dst][128:256] + ef@W1c + b1)
//   red.v4 scatter of the 128-dim HIDDEN into g_aggh[dst]  (W2 folded into GRU)
// ---------------------------------------------------------------------------
__global__ __launch_bounds__(256) void msg_kernel(
    const float* __restrict__ ef,
    const int* __restrict__ src, const int* __restrict__ dst,
    const float* __restrict__ W1, const float* __restrict__ b1)
{
    __shared__ float sW1c[EDIM][MHID];
    __shared__ float sb1[MHID];
    __shared__ int   ssrc[32], sdst[32];
    __shared__ float sef[32][EDIM];

    const int e0  = blockIdx.x * 32;
    const int tid = threadIdx.x;

    if (tid < 32) { ssrc[tid] = src[e0 + tid]; sdst[tid] = dst[e0 + tid]; }
    if (tid < 256) {
        // 32 edges x 8 feats = 256
        sef[tid >> 3][tid & 7] = ef[(long)e0 * EDIM + tid];
    }
    for (int i = tid; i < EDIM * MHID; i += 256)
        sW1c[i >> 7][i & 127] = W1[128 * MHID + i];
    if (tid < MHID) sb1[tid] = b1[tid];
    __syncthreads();

    const int e  = tid >> 3;
    const int c0 = (tid & 7) * 16;
    const int s = ssrc[e];
    const long d = sdst[e];

    const float4* ps = reinterpret_cast<const float4*>(g_P + (long)s * 256 + c0);
    const float4* pd = reinterpret_cast<const float4*>(g_P + (long)sdst[e] * 256 + 128 + c0);
    float4 pa[4], pb[4];
    #pragma unroll
    for (int i = 0; i < 4; i++) { pa[i] = ps[i]; pb[i] = pd[i]; }

    u64 efp[EDIM];
    #pragma unroll
    for (int k = 0; k < EDIM; k++) { float v = sef[e][k]; efp[k] = pack2(v, v); }

    #pragma unroll
    for (int i = 0; i < 4; i++) {
        int c = c0 + 4 * i;
        u64 v01 = pack2(pa[i].x + pb[i].x + sb1[c],     pa[i].y + pb[i].y + sb1[c + 1]);
        u64 v23 = pack2(pa[i].z + pb[i].z + sb1[c + 2], pa[i].w + pb[i].w + sb1[c + 3]);
        #pragma unroll
        for (int k = 0; k < EDIM; k++) {
            u64 w01 = *reinterpret_cast<const u64*>(&sW1c[k][c]);
            u64 w23 = *reinterpret_cast<const u64*>(&sW1c[k][c + 2]);
            v01 = fma2(efp[k], w01, v01);
            v23 = fma2(efp[k], w23, v23);
        }
        float v0, v1, v2, v3;
        unpack2(v01, v0, v1); unpack2(v23, v2, v3);
        v0 = fmaxf(v0, 0.f); v1 = fmaxf(v1, 0.f);
        v2 = fmaxf(v2, 0.f); v3 = fmaxf(v3, 0.f);
        float* p = g_aggh + d * MHID + c;
        asm volatile("red.global.add.v4.f32 [%0], {%1, %2, %3, %4};"
                     :: "l"(p), "f"(v0), "f"(v1), "f"(v2), "f"(v3) : "memory");
    }
}

// ---------------------------------------------------------------------------
// Fused GRU: gates = agg128 @ WgA + h @ Wh + deg*bvec + bg  (W2 folded in)
// then elementwise GRU, then proj (next step) or readout (last step).
// GB=32 nodes, 256 thr; warp w -> nodes {w, w+8, w+16, w+24}; lane -> cols
// lane+32j. f32x2 k-split accumulators. Consumes-and-zeroes g_aggh.
// ---------------------------------------------------------------------------
__global__ __launch_bounds__(256, 2) void gru_fused_kernel(
    const float* __restrict__ bg, const float* __restrict__ W1,
    const float* __restrict__ br1, const float* __restrict__ Wr2,
    const float* __restrict__ br2, float* __restrict__ out, int do_proj)
{
    __shared__ float sxh[GB][192];   // cols 0..127 agg128, 128..191 h_old
    const int tid  = threadIdx.x;
    const int lane = tid & 31;
    const int wid  = tid >> 5;
    const int n0   = blockIdx.x * GB;

    for (int i = tid; i < GB * MHID; i += 256) {
        int r = i >> 7, c = i & 127;
        int node = n0 + r;
        float v = 0.f;
        if (node < N_NODES) {
            long off = (long)node * MHID + c;
            v = g_aggh[off];
            g_aggh[off] = 0.f;     // ready for next step / replay
        }
        sxh[r][c] = v;
    }
    for (int i = tid; i < GB * HDIM; i += 256) {
        int r = i >> 6, c = i & 63;
        int node = n0 + r;
        sxh[r][128 + c] = (node < N_NODES) ? g_h[(long)node * HDIM + c] : 0.f;
    }
    __syncthreads();

    // accumulators: per node, k-split f32x2 per gate column
    u64 azr[4][4], acx[4][2], ach[4][2];
    #pragma unroll
    for (int n = 0; n < 4; n++) {
        #pragma unroll
        for (int j = 0; j < 4; j++) azr[n][j] = 0ull;
        acx[n][0] = acx[n][1] = 0ull;
        ach[n][0] = ach[n][1] = 0ull;
    }

    // Phase A: agg128 @ WgA (64 k-pairs)
    #pragma unroll 2
    for (int k2 = 0; k2 < 64; k2++) {
        const u64* wr = g_Wg2 + k2 * 192;
        u64 wz0 = wr[lane],       wz1 = wr[lane + 32];
        u64 wr0 = wr[lane + 64],  wr1 = wr[lane + 96];
        u64 wc0 = wr[lane + 128], wc1 = wr[lane + 160];
        #pragma unroll
        for (int n = 0; n < 4; n++) {
            u64 a = *reinterpret_cast<const u64*>(&sxh[wid + 8 * n][2 * k2]);
            azr[n][0] = fma2(a, wz0, azr[n][0]);
            azr[n][1] = fma2(a, wz1, azr[n][1]);
            azr[n][2] = fma2(a, wr0, azr[n][2]);
            azr[n][3] = fma2(a, wr1, azr[n][3]);
            acx[n][0] = fma2(a, wc0, acx[n][0]);
            acx[n][1] = fma2(a, wc1, acx[n][1]);
        }
    }
    // Phase B: h @ Wh (32 k-pairs)
    #pragma unroll 2
    for (int k2 = 0; k2 < 32; k2++) {
        const u64* wr = g_Whp + k2 * 192;
        u64 wz0 = wr[lane],       wz1 = wr[lane + 32];
        u64 wr0 = wr[lane + 64],  wr1 = wr[lane + 96];
        u64 wc0 = wr[lane + 128], wc1 = wr[lane + 160];
        #pragma unroll
        for (int n = 0; n < 4; n++) {
            u64 a = *reinterpret_cast<const u64*>(&sxh[wid + 8 * n][128 + 2 * k2]);
            azr[n][0] = fma2(a, wz0, azr[n][0]);
            azr[n][1] = fma2(a, wz1, azr[n][1]);
            azr[n][2] = fma2(a, wr0, azr[n][2]);
            azr[n][3] = fma2(a, wr1, azr[n][3]);
            ach[n][0] = fma2(a, wc0, ach[n][0]);
            ach[n][1] = fma2(a, wc1, ach[n][1]);
        }
    }

    // elementwise GRU (warp-private rows -> no block sync needed)
    {
        float bz[2] = { bg[lane],       bg[lane + 32] };
        float brg[2]= { bg[lane + 64],  bg[lane + 96] };
        float bc[2] = { bg[lane + 128], bg[lane + 160] };
        float vz[2] = { g_bvec[lane],       g_bvec[lane + 32] };
        float vr[2] = { g_bvec[lane + 64],  g_bvec[lane + 96] };
        float vc[2] = { g_bvec[lane + 128], g_bvec[lane + 160] };

        #pragma unroll
        for (int n = 0; n < 4; n++) {
            int r = wid + 8 * n;
            int node = n0 + r;
            float deg = (node < N_NODES) ? g_deg[node] : 0.f;
            #pragma unroll
            for (int j = 0; j < 2; j++) {
                int c = lane + 32 * j;
                float lo, hi, gz, gr, gcx, gch;
                unpack2(azr[n][j], lo, hi);     gz  = lo + hi;
                unpack2(azr[n][2 + j], lo, hi); gr  = lo + hi;
                unpack2(acx[n][j], lo, hi);     gcx = lo + hi;
                unpack2(ach[n][j], lo, hi);     gch = lo + hi;
                float z  = sigmoidf(gz + bz[j] + deg * vz[j]);
                float rr = sigmoidf(gr + brg[j] + deg * vr[j]);
                float hc = tanhf(gcx + bc[j] + deg * vc[j] + rr * gch);
                float hold = sxh[r][128 + c];
                float hnew = z * hold + (1.f - z) * hc;
                sxh[r][c] = hnew;               // stage for proj/readout
                if (node < N_NODES) g_h[(long)node * HDIM + c] = hnew;
            }
        }
    }

    if (do_proj) {
        // P = h_new @ [W1a|W1b], col-pair f32x2, W1 read directly (float2)
        u64 p[4][4];
        #pragma unroll
        for (int n = 0; n < 4; n++)
            #pragma unroll
            for (int j = 0; j < 4; j++) p[n][j] = 0ull;

        #pragma unroll 2
        for (int k = 0; k < 64; k++) {
            const float* w1r = W1 + (long)k * MHID;
            const float* w2r = W1 + (long)(64 + k) * MHID;
            u64 w0 = *reinterpret_cast<const u64*>(w1r + 2 * lane);
            u64 w1v= *reinterpret_cast<const u64*>(w1r + 64 + 2 * lane);
            u64 w2 = *reinterpret_cast<const u64*>(w2r + 2 * lane);
            u64 w3 = *reinterpret_cast<const u64*>(w2r + 64 + 2 * lane);
            #pragma unroll
            for (int n = 0; n < 4; n++) {
                float af = sxh[wid + 8 * n][k];
                u64 ap = pack2(af, af);
                p[n][0] = fma2(ap, w0, p[n][0]);
                p[n][1] = fma2(ap, w1v, p[n][1]);
                p[n][2] = fma2(ap, w2, p[n][2]);
                p[n][3] = fma2(ap, w3, p[n][3]);
            }
        }
        #pragma unroll
        for (int n = 0; n < 4; n++) {
            int node = n0 + wid + 8 * n;
            if (node < N_NODES) {
                float* op = g_P + (long)node * 256;
                #pragma unroll
                for (int j = 0; j < 4; j++)
                    *reinterpret_cast<u64*>(op + 64 * j + 2 * lane) = p[n][j];
            }
        }
    } else {
        // readout: relu(h_new @ Wr1 + br1) @ Wr2 + br2 (k-split f32x2)
        u64 racc[4][4];
        #pragma unroll
        for (int n = 0; n < 4; n++)
            #pragma unroll
            for (int j = 0; j < 4; j++) racc[n][j] = 0ull;

        #pragma unroll 2
        for (int k2 = 0; k2 < 32; k2++) {
            const u64* wr = g_Wr1p + k2 * 128;
            u64 w0 = wr[lane],      w1v = wr[lane + 32];
            u64 w2 = wr[lane + 64], w3 = wr[lane + 96];
            #pragma unroll
            for (int n = 0; n < 4; n++) {
                u64 a = *reinterpret_cast<const u64*>(&sxh[wid + 8 * n][2 * k2]);
                racc[n][0] = fma2(a, w0, racc[n][0]);
                racc[n][1] = fma2(a, w1v, racc[n][1]);
                racc[n][2] = fma2(a, w2, racc[n][2]);
                racc[n][3] = fma2(a, w3, racc[n][3]);
            }
        }
        float bb[4], w2v[4];
        #pragma unroll
        for (int j = 0; j < 4; j++) {
            bb[j]  = br1[lane + 32 * j];
            w2v[j] = Wr2[lane + 32 * j];
        }
        float part[4];
        #pragma unroll
        for (int n = 0; n < 4; n++) {
            float s = 0.f;
            #pragma unroll
            for (int j = 0; j < 4; j++) {
                float lo, hi; unpack2(racc[n][j], lo, hi);
                float v = fmaxf(lo + hi + bb[j], 0.f);
                s = fmaf(v, w2v[j], s);
            }
            part[n] = s;
        }
        #pragma unroll
        for (int off = 16; off; off >>= 1)
            #pragma unroll
            for (int n = 0; n < 4; n++)
                part[n] += __shfl_xor_sync(0xffffffffu, part[n], off);
        if (lane == 0) {
            float bo = br2[0];
            #pragma unroll
            for (int n = 0; n < 4; n++) {
                int node = n0 + wid + 8 * n;
                if (node < N_NODES) out[node] = part[n] + bo;
            }
        }
    }
}

extern "C" void kernel_launch(void* const* d_in, const int* in_sizes, int n_in,
                              void* d_out, int out_size) {
    const float* nf  = (const float*)d_in[0];
    const float* ef  = (const float*)d_in[1];
    const int*   src = (const int*)  d_in[2];
    const int*   dst = (const int*)  d_in[3];
    const float* W1  = (const float*)d_in[4];
    const float* b1  = (const float*)d_in[5];
    const float* W2  = (const float*)d_in[6];
    // b2 = d_in[7]
    const float* Wx  = (const float*)d_in[8];
    const float* Wh  = (const float*)d_in[9];
    const float* bg  = (const float*)d_in[10];
    const float* Wr1 = (const float*)d_in[11];
    const float* br1 = (const float*)d_in[12];
    const float* Wr2 = (const float*)d_in[13];
    const float* br2 = (const float*)d_in[14];
    const float* b2  = (const float*)d_in[7];
    float* out = (float*)d_out;

    const int nb_init = (N_NODES * MHID + 255) / 256;   // 25000
    const int nproj   = (N_NODES + PB - 1) / PB;        // 782
    const int ngru    = (N_NODES + GB - 1) / GB;        // 1563
    const int ndeg    = (N_EDGES + 255) / 256;          // 1563
    const int nmsg    = N_EDGES / 32;                   // 12500

    init_kernel<<<nb_init, 256>>>(nf);
    prep_wg<<<(64 * 192 + 255) / 256, 256>>>(W2, Wx);
    prep_pack<<<(32 * 192 + 32 * 128 + 192 + 255) / 256, 256>>>(Wh, Wr1, b2, Wx);
    deg_kernel<<<ndeg, 256>>>(dst);
    proj_kernel<<<nproj, 256>>>(W1);
    // t = 0
    msg_kernel<<<nmsg, 256>>>(ef, src, dst, W1, b1);
    gru_fused_kernel<<<ngru, 256>>>(bg, W1, br1, Wr2, br2, out, 1);
    // t = 1 (readout fused)
    msg_kernel<<<nmsg, 256>>>(ef, src, dst, W1, b1);
    gru_fused_kernel<<<ngru, 256>>>(bg, W1, br1, Wr2, br2, out, 0);
}

// round 8
// speedup vs baseline: 1.8906x; 1.5376x over previous
#include <cuda_runtime.h>
#include <cuda_bf16.h>
#include <math.h>

#define N_NODES 50000
#define N_EDGES 400000
#define HDIM 64
#define EDIM 8
#define MHID 128
#define RHID 128
#define PB 64    // nodes per block in projection kernel
#define GB 32    // nodes per block in fused GRU kernel

typedef unsigned long long u64;

// Scratch (device globals: no allocation allowed)
__device__ float g_h[N_NODES * HDIM];
__device__ float g_PA[2][N_NODES * MHID];     // h @ W1a  (src projection), double-buffered
__device__ float g_PBuf[2][N_NODES * MHID];   // h @ W1b  (dst projection), double-buffered
__device__ int   g_degi[N_NODES];
__device__ int   g_cnt[N_NODES];
__device__ int   g_rowst[N_NODES + 1];
__device__ int   g_esrc[N_EDGES];             // src per sorted position
__device__ int   g_eidx[N_EDGES];             // original edge id per position
__device__ float g_C[(long)N_EDGES * MHID];   // ef@W1c + b1 per sorted position
__device__ u64   g_Wg2[64 * 192];             // k-pairs of WgA = W2@Wx
__device__ u64   g_Whp[32 * 192];             // k-pairs of Wh
__device__ u64   g_Wr1p[32 * 128];            // k-pairs of Wr1
__device__ float g_bvec[192];                 // b2 @ Wx

__device__ __forceinline__ float sigmoidf(float x) { return 1.f / (1.f + expf(-x)); }
__device__ __forceinline__ u64 pack2(float lo, float hi) {
    u64 r; asm("mov.b64 %0, {%1, %2};" : "=l"(r) : "f"(lo), "f"(hi)); return r;
}
__device__ __forceinline__ void unpack2(u64 v, float& lo, float& hi) {
    asm("mov.b64 {%0, %1}, %2;" : "=f"(lo), "=f"(hi) : "l"(v));
}
__device__ __forceinline__ u64 fma2(u64 a, u64 b, u64 c) {
    u64 d; asm("fma.rn.f32x2 %0, %1, %2, %3;" : "=l"(d) : "l"(a), "l"(b), "l"(c)); return d;
}

__global__ void init_kernel(const float* __restrict__ nf) {
    int i = blockIdx.x * blockDim.x + threadIdx.x;
    if (i < N_NODES * HDIM) g_h[i] = nf[i];
    if (i < N_NODES) { g_degi[i] = 0; g_cnt[i] = 0; }
}

__global__ void deg_kernel(const int* __restrict__ dst) {
    int i = blockIdx.x * blockDim.x + threadIdx.x;
    if (i < N_EDGES) atomicAdd(&g_degi[dst[i]], 1);
}

// Single-block exclusive prefix sum over g_degi -> g_rowst.
__global__ __launch_bounds__(1024) void scan_kernel() {
    __shared__ int sp[1024];
    const int t = threadIdx.x;
    const int CH = (N_NODES + 1023) / 1024;   // 49
    const int base = t * CH;
    int s = 0;
    for (int i = 0; i < CH; i++) {
        int idx = base + i;
        if (idx < N_NODES) s += g_degi[idx];
    }
    sp[t] = s;
    __syncthreads();
    for (int off = 1; off < 1024; off <<= 1) {
        int v = (t >= off) ? sp[t - off] : 0;
        __syncthreads();
        sp[t] += v;
        __syncthreads();
    }
    int run = (t == 0) ? 0 : sp[t - 1];
    for (int i = 0; i < CH; i++) {
        int idx = base + i;
        if (idx < N_NODES) { g_rowst[idx] = run; run += g_degi[idx]; }
    }
    if (t == 1023) g_rowst[N_NODES] = run;
}

__global__ void scatter_kernel(const int* __restrict__ src, const int* __restrict__ dst) {
    int i = blockIdx.x * blockDim.x + threadIdx.x;
    if (i < N_EDGES) {
        int d = dst[i];
        int p = g_rowst[d] + atomicAdd(&g_cnt[d], 1);
        g_eidx[p] = i;
        g_esrc[p] = src[i];
    }
}

// C[pos] = ef[eidx[pos]] @ W1c + b1  (iteration-invariant, computed once)
__global__ __launch_bounds__(256) void csort_kernel(
    const float* __restrict__ ef, const float* __restrict__ W1,
    const float* __restrict__ b1)
{
    __shared__ float sW1c[EDIM][MHID];
    __shared__ float sb1[MHID];
    __shared__ int   sei[32];
    __shared__ float sef[32][EDIM];
    const int p0  = blockIdx.x * 32;
    const int tid = threadIdx.x;

    if (tid < 32) sei[tid] = g_eidx[p0 + tid];
    for (int i = tid; i < EDIM * MHID; i += 256)
        sW1c[i >> 7][i & 127] = W1[128 * MHID + i];
    if (tid < MHID) sb1[tid] = b1[tid];
    __syncthreads();
    { int r = tid >> 3, k = tid & 7; sef[r][k] = ef[(long)sei[r] * EDIM + k]; }
    __syncthreads();

    const int r  = tid >> 3;
    const int c0 = (tid & 7) * 16;
    const long pos = p0 + r;
    float efr[EDIM];
    #pragma unroll
    for (int k = 0; k < EDIM; k++) efr[k] = sef[r][k];

    #pragma unroll
    for (int i = 0; i < 4; i++) {
        int c = c0 + 4 * i;
        float v0 = sb1[c], v1 = sb1[c + 1], v2 = sb1[c + 2], v3 = sb1[c + 3];
        #pragma unroll
        for (int k = 0; k < EDIM; k++) {
            float e_k = efr[k];
            v0 = fmaf(e_k, sW1c[k][c + 0], v0);
            v1 = fmaf(e_k, sW1c[k][c + 1], v1);
            v2 = fmaf(e_k, sW1c[k][c + 2], v2);
            v3 = fmaf(e_k, sW1c[k][c + 3], v3);
        }
        *reinterpret_cast<float4*>(g_C + pos * MHID + c) = make_float4(v0, v1, v2, v3);
    }
}

// WgA[k][j] = sum_c W2[k][c] * Wx[c][j]; store k-pairs packed.
__global__ __launch_bounds__(256) void prep_wg(const float* __restrict__ W2,
                                               const float* __restrict__ Wx) {
    int t = blockIdx.x * blockDim.x + threadIdx.x;
    if (t >= 64 * 192) return;
    int k2 = t / 192, j = t % 192;
    float s0 = 0.f, s1 = 0.f;
    for (int c = 0; c < 64; c++) {
        float w = Wx[c * 192 + j];
        s0 = fmaf(W2[(2 * k2) * 64 + c], w, s0);
        s1 = fmaf(W2[(2 * k2 + 1) * 64 + c], w, s1);
    }
    g_Wg2[k2 * 192 + j] = pack2(s0, s1);
}

__global__ __launch_bounds__(256) void prep_pack(const float* __restrict__ Wh,
                                                 const float* __restrict__ Wr1,
                                                 const float* __restrict__ b2,
                                                 const float* __restrict__ Wx) {
    int t = blockIdx.x * blockDim.x + threadIdx.x;
    if (t < 32 * 192) {
        int i = t / 192, j = t % 192;
        g_Whp[t] = pack2(Wh[(2 * i) * 192 + j], Wh[(2 * i + 1) * 192 + j]);
    } else if (t < 32 * 192 + 32 * 128) {
        int u = t - 32 * 192;
        int i = u / 128, j = u % 128;
        g_Wr1p[u] = pack2(Wr1[(2 * i) * 128 + j], Wr1[(2 * i + 1) * 128 + j]);
    } else if (t < 32 * 192 + 32 * 128 + 192) {
        int j = t - (32 * 192 + 32 * 128);
        float s = 0.f;
        for (int c = 0; c < 64; c++) s = fmaf(b2[c], Wx[c * 192 + j], s);
        g_bvec[j] = s;
    }
}

// ---------------------------------------------------------------------------
// Standalone projection (t=0 only): PA0[n] = h[n]@W1a, PB0[n] = h[n]@W1b
// ---------------------------------------------------------------------------
__global__ __launch_bounds__(256) void proj_kernel(const float* __restrict__ W1) {
    __shared__ float sh[PB][HDIM];
    const int n0  = blockIdx.x * PB;
    const int tid = threadIdx.x;

    for (int i = tid; i < PB * HDIM; i += 256) {
        int r = i >> 6, c = i & 63;
        int node = n0 + r;
        sh[r][c] = (node < N_NODES) ? g_h[(long)node * HDIM + c] : 0.f;
    }
    __syncthreads();

    const int hc = tid & 31;
    const int nr = tid >> 5;
    const int j0 = hc * 8;
    const float* Wbase = (j0 < 128) ? (W1 + j0) : (W1 + 64 * MHID + (j0 - 128));

    float acc[8][8];
    #pragma unroll
    for (int n = 0; n < 8; n++)
        #pragma unroll
        for (int j = 0; j < 8; j++) acc[n][j] = 0.f;

    #pragma unroll 2
    for (int k = 0; k < HDIM; k++) {
        const float4* wp = reinterpret_cast<const float4*>(Wbase + (long)k * MHID);
        float4 wA = wp[0], wB = wp[1];
        #pragma unroll
        for (int n = 0; n < 8; n++) {
            float a = sh[nr + 8 * n][k];
            acc[n][0] = fmaf(a, wA.x, acc[n][0]);
            acc[n][1] = fmaf(a, wA.y, acc[n][1]);
            acc[n][2] = fmaf(a, wA.z, acc[n][2]);
            acc[n][3] = fmaf(a, wA.w, acc[n][3]);
            acc[n][4] = fmaf(a, wB.x, acc[n][4]);
            acc[n][5] = fmaf(a, wB.y, acc[n][5]);
            acc[n][6] = fmaf(a, wB.z, acc[n][6]);
            acc[n][7] = fmaf(a, wB.w, acc[n][7]);
        }
    }

    #pragma unroll
    for (int n = 0; n < 8; n++) {
        int node = n0 + nr + 8 * n;
        if (node < N_NODES) {
            float* dstp = (j0 < 128) ? (g_PA[0] + (long)node * MHID + j0)
                                     : (g_PBuf[0] + (long)node * MHID + (j0 - 128));
            float4* op = reinterpret_cast<float4*>(dstp);
            op[0] = make_float4(acc[n][0], acc[n][1], acc[n][2], acc[n][3]);
            op[1] = make_float4(acc[n][4], acc[n][5], acc[n][6], acc[n][7]);
        }
    }
}

// ---------------------------------------------------------------------------
// Fused: CSR aggregation + gates GEMM + GRU + (proj into OTHER buffer | readout).
// Reads PA/PB from buffer rbuf, writes projections to buffer (rbuf^1) —
// double buffering removes the cross-block RAW hazard.
// ---------------------------------------------------------------------------
__global__ __launch_bounds__(256, 2) void gru_fused_kernel(
    const float* __restrict__ bg, const float* __restrict__ W1,
    const float* __restrict__ br1, const float* __restrict__ Wr2,
    const float* __restrict__ br2, float* __restrict__ out,
    int rbuf, int do_proj)
{
    __shared__ float sxh[GB][192];   // cols 0..127 agg128, 128..191 h_old
    const int tid  = threadIdx.x;
    const int lane = tid & 31;
    const int wid  = tid >> 5;
    const int n0   = blockIdx.x * GB;

    const float* PAr = g_PA[rbuf];
    const float* PBr = g_PBuf[rbuf];

    // --- CSR aggregation (warp-private rows, no atomics) ---
    int degn[4];
    #pragma unroll
    for (int n = 0; n < 4; n++) {
        const int r = wid + 8 * n;
        const int node = n0 + r;
        float4 acc = make_float4(0.f, 0.f, 0.f, 0.f);
        int dg = 0;
        if (node < N_NODES) {
            int st = g_rowst[node];
            int en = g_rowst[node + 1];
            dg = en - st;
            float4 pb = *reinterpret_cast<const float4*>(PBr + (long)node * MHID + 4 * lane);
            for (int j = st; j < en; j++) {
                int s = g_esrc[j];
                float4 pa = *reinterpret_cast<const float4*>(PAr + (long)s * MHID + 4 * lane);
                float4 cc = *reinterpret_cast<const float4*>(g_C + (long)j * MHID + 4 * lane);
                acc.x += fmaxf(pa.x + pb.x + cc.x, 0.f);
                acc.y += fmaxf(pa.y + pb.y + cc.y, 0.f);
                acc.z += fmaxf(pa.z + pb.z + cc.z, 0.f);
                acc.w += fmaxf(pa.w + pb.w + cc.w, 0.f);
            }
            float2 hv = *reinterpret_cast<const float2*>(g_h + (long)node * HDIM + 2 * lane);
            sxh[r][128 + 2 * lane]     = hv.x;
            sxh[r][128 + 2 * lane + 1] = hv.y;
        } else {
            sxh[r][128 + 2 * lane]     = 0.f;
            sxh[r][128 + 2 * lane + 1] = 0.f;
        }
        degn[n] = dg;
        *reinterpret_cast<float4*>(&sxh[r][4 * lane]) = acc;
    }
    __syncwarp();

    // --- gates GEMM: k-split f32x2 accumulators ---
    u64 azr[4][4], acx[4][2], ach[4][2];
    #pragma unroll
    for (int n = 0; n < 4; n++) {
        #pragma unroll
        for (int j = 0; j < 4; j++) azr[n][j] = 0ull;
        acx[n][0] = acx[n][1] = 0ull;
        ach[n][0] = ach[n][1] = 0ull;
    }

    #pragma unroll 2
    for (int k2 = 0; k2 < 64; k2++) {        // agg128 @ WgA
        const u64* wr = g_Wg2 + k2 * 192;
        u64 wz0 = wr[lane],       wz1 = wr[lane + 32];
        u64 wr0 = wr[lane + 64],  wr1 = wr[lane + 96];
        u64 wc0 = wr[lane + 128], wc1 = wr[lane + 160];
        #pragma unroll
        for (int n = 0; n < 4; n++) {
            u64 a = *reinterpret_cast<const u64*>(&sxh[wid + 8 * n][2 * k2]);
            azr[n][0] = fma2(a, wz0, azr[n][0]);
            azr[n][1] = fma2(a, wz1, azr[n][1]);
            azr[n][2] = fma2(a, wr0, azr[n][2]);
            azr[n][3] = fma2(a, wr1, azr[n][3]);
            acx[n][0] = fma2(a, wc0, acx[n][0]);
            acx[n][1] = fma2(a, wc1, acx[n][1]);
        }
    }
    #pragma unroll 2
    for (int k2 = 0; k2 < 32; k2++) {        // h @ Wh
        const u64* wr = g_Whp + k2 * 192;
        u64 wz0 = wr[lane],       wz1 = wr[lane + 32];
        u64 wr0 = wr[lane + 64],  wr1 = wr[lane + 96];
        u64 wc0 = wr[lane + 128], wc1 = wr[lane + 160];
        #pragma unroll
        for (int n = 0; n < 4; n++) {
            u64 a = *reinterpret_cast<const u64*>(&sxh[wid + 8 * n][128 + 2 * k2]);
            azr[n][0] = fma2(a, wz0, azr[n][0]);
            azr[n][1] = fma2(a, wz1, azr[n][1]);
            azr[n][2] = fma2(a, wr0, azr[n][2]);
            azr[n][3] = fma2(a, wr1, azr[n][3]);
            ach[n][0] = fma2(a, wc0, ach[n][0]);
            ach[n][1] = fma2(a, wc1, ach[n][1]);
        }
    }

    // --- elementwise GRU ---
    {
        float bz[2] = { bg[lane],       bg[lane + 32] };
        float brg[2]= { bg[lane + 64],  bg[lane + 96] };
        float bc[2] = { bg[lane + 128], bg[lane + 160] };
        float vz[2] = { g_bvec[lane],       g_bvec[lane + 32] };
        float vr[2] = { g_bvec[lane + 64],  g_bvec[lane + 96] };
        float vc[2] = { g_bvec[lane + 128], g_bvec[lane + 160] };

        #pragma unroll
        for (int n = 0; n < 4; n++) {
            int r = wid + 8 * n;
            int node = n0 + r;
            float deg = (float)degn[n];
            #pragma unroll
            for (int j = 0; j < 2; j++) {
                int c = lane + 32 * j;
                float lo, hi, gz, gr, gcx, gch;
                unpack2(azr[n][j], lo, hi);     gz  = lo + hi;
                unpack2(azr[n][2 + j], lo, hi); gr  = lo + hi;
                unpack2(acx[n][j], lo, hi);     gcx = lo + hi;
                unpack2(ach[n][j], lo, hi);     gch = lo + hi;
                float z  = sigmoidf(gz + bz[j] + deg * vz[j]);
                float rr = sigmoidf(gr + brg[j] + deg * vr[j]);
                float hc = tanhf(gcx + bc[j] + deg * vc[j] + rr * gch);
                float hold = sxh[r][128 + c];
                float hnew = z * hold + (1.f - z) * hc;
                sxh[r][c] = hnew;               // stage for proj/readout
                if (node < N_NODES) g_h[(long)node * HDIM + c] = hnew;
            }
        }
    }
    __syncwarp();

    if (do_proj) {
        // PA/PB(rbuf^1) = h_new @ [W1a | W1b], col-pair f32x2
        float* PAw = g_PA[rbuf ^ 1];
        float* PBw = g_PBuf[rbuf ^ 1];
        u64 p[4][4];
        #pragma unroll
        for (int n = 0; n < 4; n++)
            #pragma unroll
            for (int j = 0; j < 4; j++) p[n][j] = 0ull;

        #pragma unroll 2
        for (int k = 0; k < 64; k++) {
            const float* w1r = W1 + (long)k * MHID;
            const float* w2r = W1 + (long)(64 + k) * MHID;
            u64 w0 = *reinterpret_cast<const u64*>(w1r + 2 * lane);
            u64 w1v= *reinterpret_cast<const u64*>(w1r + 64 + 2 * lane);
            u64 w2 = *reinterpret_cast<const u64*>(w2r + 2 * lane);
            u64 w3 = *reinterpret_cast<const u64*>(w2r + 64 + 2 * lane);
            #pragma unroll
            for (int n = 0; n < 4; n++) {
                float af = sxh[wid + 8 * n][k];
                u64 ap = pack2(af, af);
                p[n][0] = fma2(ap, w0, p[n][0]);
                p[n][1] = fma2(ap, w1v, p[n][1]);
                p[n][2] = fma2(ap, w2, p[n][2]);
                p[n][3] = fma2(ap, w3, p[n][3]);
            }
        }
        #pragma unroll
        for (int n = 0; n < 4; n++) {
            int node = n0 + wid + 8 * n;
            if (node < N_NODES) {
                float* pa = PAw + (long)node * MHID;
                float* pb = PBw + (long)node * MHID;
                *reinterpret_cast<u64*>(pa + 2 * lane)      = p[n][0];
                *reinterpret_cast<u64*>(pa + 64 + 2 * lane) = p[n][1];
                *reinterpret_cast<u64*>(pb + 2 * lane)      = p[n][2];
                *reinterpret_cast<u64*>(pb + 64 + 2 * lane) = p[n][3];
            }
        }
    } else {
        // readout: relu(h_new @ Wr1 + br1) @ Wr2 + br2 (k-split f32x2)
        u64 racc[4][4];
        #pragma unroll
        for (int n = 0; n < 4; n++)
            #pragma unroll
            for (int j = 0; j < 4; j++) racc[n][j] = 0ull;

        #pragma unroll 2
        for (int k2 = 0; k2 < 32; k2++) {
            const u64* wr = g_Wr1p + k2 * 128;
            u64 w0 = wr[lane],      w1v = wr[lane + 32];
            u64 w2 = wr[lane + 64], w3 = wr[lane + 96];
            #pragma unroll
            for (int n = 0; n < 4; n++) {
                u64 a = *reinterpret_cast<const u64*>(&sxh[wid + 8 * n][2 * k2]);
                racc[n][0] = fma2(a, w0, racc[n][0]);
                racc[n][1] = fma2(a, w1v, racc[n][1]);
                racc[n][2] = fma2(a, w2, racc[n][2]);
                racc[n][3] = fma2(a, w3, racc[n][3]);
            }
        }
        float bb[4], w2v[4];
        #pragma unroll
        for (int j = 0; j < 4; j++) {
            bb[j]  = br1[lane + 32 * j];
            w2v[j] = Wr2[lane + 32 * j];
        }
        float part[4];
        #pragma unroll
        for (int n = 0; n < 4; n++) {
            float s = 0.f;
            #pragma unroll
            for (int j = 0; j < 4; j++) {
                float lo, hi; unpack2(racc[n][j], lo, hi);
                float v = fmaxf(lo + hi + bb[j], 0.f);
                s = fmaf(v, w2v[j], s);
            }
            part[n] = s;
        }
        #pragma unroll
        for (int off = 16; off; off >>= 1)
            #pragma unroll
            for (int n = 0; n < 4; n++)
                part[n] += __shfl_xor_sync(0xffffffffu, part[n], off);
        if (lane == 0) {
            float bo = br2[0];
            #pragma unroll
            for (int n = 0; n < 4; n++) {
                int node = n0 + wid + 8 * n;
                if (node < N_NODES) out[node] = part[n] + bo;
            }
        }
    }
}

extern "C" void kernel_launch(void* const* d_in, const int* in_sizes, int n_in,
                              void* d_out, int out_size) {
    const float* nf  = (const float*)d_in[0];
    const float* ef  = (const float*)d_in[1];
    const int*   src = (const int*)  d_in[2];
    const int*   dst = (const int*)  d_in[3];
    const float* W1  = (const float*)d_in[4];
    const float* b1  = (const float*)d_in[5];
    const float* W2  = (const float*)d_in[6];
    const float* b2  = (const float*)d_in[7];
    const float* Wx  = (const float*)d_in[8];
    const float* Wh  = (const float*)d_in[9];
    const float* bg  = (const float*)d_in[10];
    const float* Wr1 = (const float*)d_in[11];
    const float* br1 = (const float*)d_in[12];
    const float* Wr2 = (const float*)d_in[13];
    const float* br2 = (const float*)d_in[14];
    float* out = (float*)d_out;

    const int nb_init = (N_NODES * HDIM + 255) / 256;   // 12500
    const int nproj   = (N_NODES + PB - 1) / PB;        // 782
    const int ngru    = (N_NODES + GB - 1) / GB;        // 1563
    const int nedge   = (N_EDGES + 255) / 256;          // 1563
    const int ncsort  = N_EDGES / 32;                   // 12500

    init_kernel<<<nb_init, 256>>>(nf);
    prep_wg<<<(64 * 192 + 255) / 256, 256>>>(W2, Wx);
    prep_pack<<<(32 * 192 + 32 * 128 + 192 + 255) / 256, 256>>>(Wh, Wr1, b2, Wx);
    deg_kernel<<<nedge, 256>>>(dst);
    scan_kernel<<<1, 1024>>>();
    scatter_kernel<<<nedge, 256>>>(src, dst);
    csort_kernel<<<ncsort, 256>>>(ef, W1, b1);
    proj_kernel<<<nproj, 256>>>(W1);
    // t = 0: read buf0, write projections to buf1
    gru_fused_kernel<<<ngru, 256>>>(bg, W1, br1, Wr2, br2, out, 0, 1);
    // t = 1: read buf1, readout
    gru_fused_kernel<<<ngru, 256>>>(bg, W1, br1, Wr2, br2, out, 1, 0);
}